// round 7
// baseline (speedup 1.0000x reference)
#include <cuda_runtime.h>

#define DIMC 512
#define NH   8
#define HD   64
#define BATCH 4
#define NQ   1024
#define NKV  1024

// ---------------- scratch (device globals: no allocation allowed) ----------
__device__ float g_q [BATCH*NH*NQ *HD];   // stored pre-rounded to tf32 pattern
__device__ float g_k [BATCH*NH*NKV*HD];   // "
__device__ float g_v [BATCH*NH*NKV*HD];   // "
__device__ float g_xo[BATCH*NQ*DIMC];
__device__ float g_lam[NH/2];

// ---------------- lambda ---------------------------------------------------
__global__ void lam_kernel(const float* __restrict__ lq1, const float* __restrict__ lk1,
                           const float* __restrict__ lq2, const float* __restrict__ lk2)
{
    int p = threadIdx.x;
    if (p < NH/2) {
        float a = 0.f, c = 0.f;
        for (int d = 0; d < HD; d++) {
            a += lq1[p*HD+d] * lk1[p*HD+d];
            c += lq2[p*HD+d] * lk2[p*HD+d];
        }
        g_lam[p] = __expf(a) - __expf(c) + 0.8f;
    }
}

// ---------------- tf32 helpers ---------------------------------------------
__device__ __forceinline__ unsigned f2tf32(float x) {
    unsigned r;
    asm("cvt.rna.tf32.f32 %0, %1;" : "=r"(r) : "f"(x));
    return r;
}

__device__ __forceinline__ void mma_tf32(float c[4],
    unsigned a0, unsigned a1, unsigned a2, unsigned a3,
    unsigned b0, unsigned b1)
{
    asm volatile(
        "mma.sync.aligned.m16n8k8.row.col.f32.tf32.tf32.f32 "
        "{%0,%1,%2,%3},{%4,%5,%6,%7},{%8,%9},{%0,%1,%2,%3};\n"
        : "+f"(c[0]), "+f"(c[1]), "+f"(c[2]), "+f"(c[3])
        : "r"(a0), "r"(a1), "r"(a2), "r"(a3), "r"(b0), "r"(b1));
}

// ---------------- tf32 GEMM: C = A[M,K] @ W[N,K]^T + bias ------------------
// CTA tile 64x64, 128 threads (4 warps 2x2, warp tile 32x32), k-step 32,
// double-buffered smem (one sync per k-iter).
// mode 0: C row-major [M,512] (plain fp32)
// mode 1: C into [B,H,N,HD] layout, values pre-rounded to tf32 pattern
__device__ __forceinline__ void gemm_body(
    const float* __restrict__ A, const float* __restrict__ W,
    const float* __restrict__ bias, float* __restrict__ C,
    int mode, int bm, int bn)
{
    __shared__ unsigned As[2][32][72];   // [buf][k][m]
    __shared__ unsigned Ws[2][32][72];   // [buf][k][n]

    int tid  = threadIdx.x;
    int wid  = tid >> 5;
    int lane = tid & 31;
    int g    = lane >> 2;
    int tg   = lane & 3;
    int wm   = (wid >> 1) * 32;
    int wn   = (wid & 1) * 32;

    float acc[2][4][4];
#pragma unroll
    for (int mf = 0; mf < 2; mf++)
#pragma unroll
        for (int nf = 0; nf < 4; nf++)
#pragma unroll
            for (int e = 0; e < 4; e++) acc[mf][nf][e] = 0.f;

    int row = tid & 63;            // 0..63
    int ks  = (tid >> 6) * 16;     // 0 or 16
    const float* Arow = A + (size_t)(bm + row) * DIMC + ks;
    const float* Wrow = W + (size_t)(bn + row) * DIMC + ks;

    float4 av[4], wv[4];
#pragma unroll
    for (int i = 0; i < 4; i++) {
        av[i] = *(const float4*)(Arow + 4*i);
        wv[i] = *(const float4*)(Wrow + 4*i);
    }
    // stage buffer 0
#pragma unroll
    for (int j = 0; j < 4; j++) {
        As[0][ks+4*j+0][row] = f2tf32(av[j].x);
        As[0][ks+4*j+1][row] = f2tf32(av[j].y);
        As[0][ks+4*j+2][row] = f2tf32(av[j].z);
        As[0][ks+4*j+3][row] = f2tf32(av[j].w);
        Ws[0][ks+4*j+0][row] = f2tf32(wv[j].x);
        Ws[0][ks+4*j+1][row] = f2tf32(wv[j].y);
        Ws[0][ks+4*j+2][row] = f2tf32(wv[j].z);
        Ws[0][ks+4*j+3][row] = f2tf32(wv[j].w);
    }
    __syncthreads();

    for (int k0 = 0; k0 < DIMC; k0 += 32) {
        int  buf  = (k0 >> 5) & 1;
        bool more = (k0 + 32 < DIMC);
        if (more) {
#pragma unroll
            for (int i = 0; i < 4; i++) {
                av[i] = *(const float4*)(Arow + k0 + 32 + 4*i);
                wv[i] = *(const float4*)(Wrow + k0 + 32 + 4*i);
            }
        }
        // compute on current buffer
#pragma unroll
        for (int ko = 0; ko < 32; ko += 8) {
            unsigned af[2][4], bf[4][2];
#pragma unroll
            for (int mf = 0; mf < 2; mf++) {
                int m0 = wm + mf*16 + g;
                af[mf][0] = As[buf][ko+tg  ][m0];
                af[mf][1] = As[buf][ko+tg  ][m0+8];
                af[mf][2] = As[buf][ko+tg+4][m0];
                af[mf][3] = As[buf][ko+tg+4][m0+8];
            }
#pragma unroll
            for (int nf = 0; nf < 4; nf++) {
                int n0 = wn + nf*8 + g;
                bf[nf][0] = Ws[buf][ko+tg  ][n0];
                bf[nf][1] = Ws[buf][ko+tg+4][n0];
            }
#pragma unroll
            for (int mf = 0; mf < 2; mf++)
#pragma unroll
                for (int nf = 0; nf < 4; nf++)
                    mma_tf32(acc[mf][nf], af[mf][0], af[mf][1], af[mf][2], af[mf][3],
                             bf[nf][0], bf[nf][1]);
        }
        if (more) {
            int nb = buf ^ 1;
#pragma unroll
            for (int j = 0; j < 4; j++) {
                As[nb][ks+4*j+0][row] = f2tf32(av[j].x);
                As[nb][ks+4*j+1][row] = f2tf32(av[j].y);
                As[nb][ks+4*j+2][row] = f2tf32(av[j].z);
                As[nb][ks+4*j+3][row] = f2tf32(av[j].w);
                Ws[nb][ks+4*j+0][row] = f2tf32(wv[j].x);
                Ws[nb][ks+4*j+1][row] = f2tf32(wv[j].y);
                Ws[nb][ks+4*j+2][row] = f2tf32(wv[j].z);
                Ws[nb][ks+4*j+3][row] = f2tf32(wv[j].w);
            }
            __syncthreads();
        }
    }

    // ---- epilogue ----
#pragma unroll
    for (int nf = 0; nf < 4; nf++) {
        int c0 = bn + wn + nf*8 + 2*tg;
        float b0 = bias[c0], b1 = bias[c0+1];
#pragma unroll
        for (int mf = 0; mf < 2; mf++) {
            int r0 = bm + wm + mf*16 + g;
            float2 o0, o1;
            o0.x = acc[mf][nf][0] + b0; o0.y = acc[mf][nf][1] + b1;
            o1.x = acc[mf][nf][2] + b0; o1.y = acc[mf][nf][3] + b1;
            if (mode == 0) {
                *(float2*)(C + (size_t)r0*DIMC + c0)     = o0;
                *(float2*)(C + (size_t)(r0+8)*DIMC + c0) = o1;
            } else {
                // pre-round to tf32 bit pattern for the attention kernel
                o0.x = __uint_as_float(f2tf32(o0.x));
                o0.y = __uint_as_float(f2tf32(o0.y));
                o1.x = __uint_as_float(f2tf32(o1.x));
                o1.y = __uint_as_float(f2tf32(o1.y));
                int h = c0 >> 6, hd = c0 & 63;
                int b_  = r0 >> 10, nq = r0 & 1023;
                *(float2*)(C + (((size_t)(b_*NH + h)*NQ + nq)*HD + hd)) = o0;
                b_ = (r0+8) >> 10; nq = (r0+8) & 1023;
                *(float2*)(C + (((size_t)(b_*NH + h)*NQ + nq)*HD + hd)) = o1;
            }
        }
    }
}

__global__ __launch_bounds__(128) void qkv_kernel(
    const float* __restrict__ x_q, const float* __restrict__ x_kv,
    const float* __restrict__ Wq, const float* __restrict__ bq,
    const float* __restrict__ Wk, const float* __restrict__ bk,
    const float* __restrict__ Wv, const float* __restrict__ bv)
{
    int z = blockIdx.z;
    const float* A    = (z == 0) ? x_q : x_kv;
    const float* W    = (z == 0) ? Wq : (z == 1) ? Wk : Wv;
    const float* bias = (z == 0) ? bq : (z == 1) ? bk : bv;
    float* C          = (z == 0) ? g_q : (z == 1) ? g_k : g_v;
    gemm_body(A, W, bias, C, 1, blockIdx.x*64, blockIdx.y*64);
}

__global__ __launch_bounds__(128) void proj_kernel(
    const float* __restrict__ Wp, const float* __restrict__ bp, float* __restrict__ out)
{
    gemm_body(g_xo, Wp, bp, out, 0, blockIdx.x*64, blockIdx.y*64);
}

// ---------------- tensor-core differential flash attention -----------------
// grid (NQ/32, NH/2, B), 128 threads (4 warps), 2 CTAs/SM.
// Score duty : warp w -> head (w>>1), m-strip (w&1)*16   (16 q-rows x 64 kv)
// PV duty    : warp w -> m-strip (w&1)*16, n-half (w>>1)*32
// Q/K/V are pre-rounded tf32 bit patterns: staging is a pure bit copy.
#define ASTRIDE 68
#define BQ 32

__global__ __launch_bounds__(128, 2) void attn_kernel(
    const int* __restrict__ coords_q, const int* __restrict__ coords_k,
    const float* __restrict__ alpha_map, const float* __restrict__ rpe)
{
    extern __shared__ __align__(16) unsigned su[];
    unsigned* sQ1 = su;                 // [32][68]
    unsigned* sQ2 = sQ1 + BQ*ASTRIDE;
    unsigned* sK1 = sQ2 + BQ*ASTRIDE;   // [64][68]
    unsigned* sK2 = sK1 + 64*ASTRIDE;
    unsigned* sV1 = sK2 + 64*ASTRIDE;
    unsigned* sV2 = sV1 + 64*ASTRIDE;
    unsigned* sS1 = sV2 + 64*ASTRIDE;   // P tiles [32][68] (tf32)
    unsigned* sS2 = sS1 + BQ*ASTRIDE;
    float* sC1 = (float*)(sS2 + BQ*ASTRIDE);  // [32] per-tile corrections
    float* sC2 = sC1 + BQ;
    float* sL1 = sC2 + BQ;                    // [32] final l
    float* sL2 = sL1 + BQ;
    int*   sCk = (int*)(sL2 + BQ);            // [64][2]

    int tid  = threadIdx.x;
    int w    = tid >> 5;
    int lane = tid & 31;
    int g    = lane >> 2;
    int tg   = lane & 3;

    int qb = blockIdx.x * BQ;
    int p  = blockIdx.y;
    int b  = blockIdx.z;
    int h1 = p, h2 = p + 4;

    // roles
    int sh  = w >> 1;          // score head (0 -> h1, 1 -> h2)
    int sm0 = (w & 1) * 16;    // score m-strip
    int pm0 = (w & 1) * 16;    // PV m-strip
    int pn0 = (w >> 1) * 32;   // PV n-half

    // ---- stage Q (bit copy; already tf32 pattern) ----
    {
        const unsigned* q1g = (const unsigned*)(g_q + ((size_t)(b*NH+h1)*NQ + qb)*HD);
        const unsigned* q2g = (const unsigned*)(g_q + ((size_t)(b*NH+h2)*NQ + qb)*HD);
#pragma unroll
        for (int c = tid; c < BQ*16; c += 128) {
            int row = c >> 4, seg = (c & 15) * 4;
            *(uint4*)&sQ1[row*ASTRIDE+seg] = *(const uint4*)(q1g + row*HD + seg);
            *(uint4*)&sQ2[row*ASTRIDE+seg] = *(const uint4*)(q2g + row*HD + seg);
        }
    }

    // score-duty per-thread query coords (rows sm0+g, sm0+g+8)
    int sr0 = sm0 + g, sr1 = sm0 + g + 8;
    int cqx0 = coords_q[((size_t)b*NQ + qb + sr0)*2];
    int cqy0 = coords_q[((size_t)b*NQ + qb + sr0)*2 + 1];
    int cqx1 = coords_q[((size_t)b*NQ + qb + sr1)*2];
    int cqy1 = coords_q[((size_t)b*NQ + qb + sr1)*2 + 1];
    int hh = sh ? h2 : h1;

    float mOld0 = -1e30f, mOld1 = -1e30f, lRun0 = 0.f, lRun1 = 0.f;

    float pacc[3][4][4];
#pragma unroll
    for (int pr = 0; pr < 3; pr++)
#pragma unroll
        for (int nt = 0; nt < 4; nt++)
#pragma unroll
            for (int e = 0; e < 4; e++) pacc[pr][nt][e] = 0.f;

    const unsigned* k1base = (const unsigned*)(g_k + ((size_t)(b*NH+h1)*NKV)*HD);
    const unsigned* k2base = (const unsigned*)(g_k + ((size_t)(b*NH+h2)*NKV)*HD);
    const unsigned* v1base = (const unsigned*)(g_v + ((size_t)(b*NH+h1)*NKV)*HD);
    const unsigned* v2base = (const unsigned*)(g_v + ((size_t)(b*NH+h2)*NKV)*HD);

    const unsigned* Qs = sh ? sQ2 : sQ1;
    const unsigned* Ks = sh ? sK2 : sK1;
    unsigned* Ss       = sh ? sS2 : sS1;
    float* sCa         = sh ? sC2 : sC1;

    for (int kb = 0; kb < NKV; kb += 64) {
        // ---- stage K/V (bit copy) + coords ----
#pragma unroll
        for (int c = tid; c < 1024; c += 128) {
            int row = c >> 4, seg = (c & 15) * 4;
            int go = (kb + row)*HD + seg;
            *(uint4*)&sK1[row*ASTRIDE+seg] = *(const uint4*)(k1base + go);
            *(uint4*)&sK2[row*ASTRIDE+seg] = *(const uint4*)(k2base + go);
            *(uint4*)&sV1[row*ASTRIDE+seg] = *(const uint4*)(v1base + go);
            *(uint4*)&sV2[row*ASTRIDE+seg] = *(const uint4*)(v2base + go);
        }
        sCk[tid] = coords_k[((size_t)b*NKV + kb)*2 + tid];
        __syncthreads();

        // ---- scores: m16 strip x 64 kv via mma ----
        float sc[8][4];
#pragma unroll
        for (int nt = 0; nt < 8; nt++)
#pragma unroll
            for (int e = 0; e < 4; e++) sc[nt][e] = 0.f;

#pragma unroll
        for (int ko = 0; ko < 64; ko += 8) {
            unsigned a0 = Qs[(sm0+g  )*ASTRIDE + ko+tg];
            unsigned a1 = Qs[(sm0+g+8)*ASTRIDE + ko+tg];
            unsigned a2 = Qs[(sm0+g  )*ASTRIDE + ko+tg+4];
            unsigned a3 = Qs[(sm0+g+8)*ASTRIDE + ko+tg+4];
#pragma unroll
            for (int nt = 0; nt < 8; nt++) {
                unsigned b0 = Ks[(8*nt+g)*ASTRIDE + ko+tg];
                unsigned b1 = Ks[(8*nt+g)*ASTRIDE + ko+tg+4];
                mma_tf32(sc[nt], a0, a1, a2, a3, b0, b1);
            }
        }

        // ---- scale + RPE bias ----
#pragma unroll
        for (int nt = 0; nt < 8; nt++) {
#pragma unroll
            for (int u = 0; u < 2; u++) {
                int col = 8*nt + 2*tg + u;
                int ckx = sCk[col*2], cky = sCk[col*2+1];
                int r0 = min(max(cqx0 - ckx + 128, 0), 256);
                int r1 = min(max(cqy0 - cky + 128, 0), 256);
                sc[nt][u] = sc[nt][u]*0.125f + __ldg(&rpe[(r0*257 + r1)*NH + hh]);
                r0 = min(max(cqx1 - ckx + 128, 0), 256);
                r1 = min(max(cqy1 - cky + 128, 0), 256);
                sc[nt][2+u] = sc[nt][2+u]*0.125f + __ldg(&rpe[(r0*257 + r1)*NH + hh]);
            }
        }

        // ---- online softmax (rows sr0, sr1; quad reduction) ----
        float rm0 = sc[0][0], rm1 = sc[0][2];
#pragma unroll
        for (int nt = 0; nt < 8; nt++) {
            rm0 = fmaxf(rm0, fmaxf(sc[nt][0], sc[nt][1]));
            rm1 = fmaxf(rm1, fmaxf(sc[nt][2], sc[nt][3]));
        }
#pragma unroll
        for (int o = 1; o < 4; o <<= 1) {
            rm0 = fmaxf(rm0, __shfl_xor_sync(0xffffffffu, rm0, o));
            rm1 = fmaxf(rm1, __shfl_xor_sync(0xffffffffu, rm1, o));
        }
        float nm0 = fmaxf(mOld0, rm0), nm1 = fmaxf(mOld1, rm1);
        float corr0 = __expf(mOld0 - nm0), corr1 = __expf(mOld1 - nm1);

        float sum0 = 0.f, sum1 = 0.f;
#pragma unroll
        for (int nt = 0; nt < 8; nt++) {
#pragma unroll
            for (int u = 0; u < 2; u++) {
                int col = 8*nt + 2*tg + u;
                float e0 = __expf(sc[nt][u]   - nm0); sum0 += e0;
                float e1 = __expf(sc[nt][2+u] - nm1); sum1 += e1;
                Ss[sr0*ASTRIDE + col] = f2tf32(e0);
                Ss[sr1*ASTRIDE + col] = f2tf32(e1);
            }
        }
#pragma unroll
        for (int o = 1; o < 4; o <<= 1) {
            sum0 += __shfl_xor_sync(0xffffffffu, sum0, o);
            sum1 += __shfl_xor_sync(0xffffffffu, sum1, o);
        }
        lRun0 = lRun0*corr0 + sum0;
        lRun1 = lRun1*corr1 + sum1;
        mOld0 = nm0; mOld1 = nm1;
        if (tg == 0) { sCa[sr0] = corr0; sCa[sr1] = corr1; }
        __syncthreads();

        // ---- PV: rescale accumulators, then mma-accumulate this tile ----
        float c1r0 = sC1[pm0+g], c1r1 = sC1[pm0+g+8];
        float c2r0 = sC2[pm0+g], c2r1 = sC2[pm0+g+8];
#pragma unroll
        for (int nt = 0; nt < 4; nt++) {
            pacc[0][nt][0] *= c1r0; pacc[0][nt][1] *= c1r0;
            pacc[0][nt][2] *= c1r1; pacc[0][nt][3] *= c1r1;
            pacc[1][nt][0] *= c2r0; pacc[1][nt][1] *= c2r0;
            pacc[1][nt][2] *= c2r1; pacc[1][nt][3] *= c2r1;
            pacc[2][nt][0] *= c2r0; pacc[2][nt][1] *= c2r0;
            pacc[2][nt][2] *= c2r1; pacc[2][nt][3] *= c2r1;
        }

#pragma unroll
        for (int ko = 0; ko < 64; ko += 8) {
            unsigned p1a0 = sS1[(pm0+g  )*ASTRIDE + ko+tg];
            unsigned p1a1 = sS1[(pm0+g+8)*ASTRIDE + ko+tg];
            unsigned p1a2 = sS1[(pm0+g  )*ASTRIDE + ko+tg+4];
            unsigned p1a3 = sS1[(pm0+g+8)*ASTRIDE + ko+tg+4];
            unsigned p2a0 = sS2[(pm0+g  )*ASTRIDE + ko+tg];
            unsigned p2a1 = sS2[(pm0+g+8)*ASTRIDE + ko+tg];
            unsigned p2a2 = sS2[(pm0+g  )*ASTRIDE + ko+tg+4];
            unsigned p2a3 = sS2[(pm0+g+8)*ASTRIDE + ko+tg+4];
#pragma unroll
            for (int nt = 0; nt < 4; nt++) {
                int n0 = pn0 + 8*nt;
                unsigned bv10 = sV1[(ko+tg  )*ASTRIDE + n0+g];
                unsigned bv11 = sV1[(ko+tg+4)*ASTRIDE + n0+g];
                unsigned bv20 = sV2[(ko+tg  )*ASTRIDE + n0+g];
                unsigned bv21 = sV2[(ko+tg+4)*ASTRIDE + n0+g];
                mma_tf32(pacc[0][nt], p1a0, p1a1, p1a2, p1a3, bv10, bv11);
                mma_tf32(pacc[1][nt], p2a0, p2a1, p2a2, p2a3, bv10, bv11);
                mma_tf32(pacc[2][nt], p2a0, p2a1, p2a2, p2a3, bv20, bv21);
            }
        }
        __syncthreads();
    }

    // publish final l
    if (tg == 0) {
        if (sh == 0) { sL1[sr0] = lRun0; sL1[sr1] = lRun1; }
        else         { sL2[sr0] = lRun0; sL2[sr1] = lRun1; }
    }
    __syncthreads();

    // ---- epilogue (PV layout) ----
    float lam = g_lam[p];
    int r_0 = pm0 + g, r_1 = pm0 + g + 8;
    float l1_0 = sL1[r_0], l1_1 = sL1[r_1];
    float l2_0 = sL2[r_0], l2_1 = sL2[r_1];
    float al0 = alpha_map[(size_t)b*NQ + qb + r_0];
    float al1 = alpha_map[(size_t)b*NQ + qb + r_1];
    float w1_0 = (1.f + al0) / l1_0, w2_0 = -al0 * lam / l2_0, i2_0 = 1.f / l2_0;
    float w1_1 = (1.f + al1) / l1_1, w2_1 = -al1 * lam / l2_1, i2_1 = 1.f / l2_1;

    float* o0 = g_xo + ((size_t)(b*NQ + qb + r_0))*DIMC;
    float* o1 = g_xo + ((size_t)(b*NQ + qb + r_1))*DIMC;
#pragma unroll
    for (int nt = 0; nt < 4; nt++) {
        int col = pn0 + 8*nt + 2*tg;
        float2 t;
        t.x = w1_0*pacc[0][nt][0] + w2_0*pacc[1][nt][0];
        t.y = w1_0*pacc[0][nt][1] + w2_0*pacc[1][nt][1];
        *(float2*)(o0 + h1*HD + col) = t;
        t.x = w1_1*pacc[0][nt][2] + w2_1*pacc[1][nt][2];
        t.y = w1_1*pacc[0][nt][3] + w2_1*pacc[1][nt][3];
        *(float2*)(o1 + h1*HD + col) = t;
        t.x = i2_0*pacc[2][nt][0];
        t.y = i2_0*pacc[2][nt][1];
        *(float2*)(o0 + h2*HD + col) = t;
        t.x = i2_1*pacc[2][nt][2];
        t.y = i2_1*pacc[2][nt][3];
        *(float2*)(o1 + h2*HD + col) = t;
    }
}

// ---------------- launch ---------------------------------------------------
#define ATT_SMEM ((4*BQ*ASTRIDE + 4*64*ASTRIDE)*4 + 4*BQ*4 + 128*4)

extern "C" void kernel_launch(void* const* d_in, const int* in_sizes, int n_in,
                              void* d_out, int out_size)
{
    const float* x_q      = (const float*)d_in[0];
    const float* x_kv     = (const float*)d_in[1];
    const int*   coords_q = (const int*)  d_in[2];
    const int*   coords_k = (const int*)  d_in[3];
    const float* alpha    = (const float*)d_in[4];
    const float* Wq       = (const float*)d_in[5];
    const float* bq       = (const float*)d_in[6];
    const float* Wk       = (const float*)d_in[7];
    const float* bk       = (const float*)d_in[8];
    const float* Wv       = (const float*)d_in[9];
    const float* bv       = (const float*)d_in[10];
    const float* lq1      = (const float*)d_in[11];
    const float* lk1      = (const float*)d_in[12];
    const float* lq2      = (const float*)d_in[13];
    const float* lk2      = (const float*)d_in[14];
    const float* rpe      = (const float*)d_in[15];
    const float* Wp       = (const float*)d_in[16];
    const float* bp       = (const float*)d_in[17];
    float* out = (float*)d_out;

    cudaFuncSetAttribute(attn_kernel,
                         cudaFuncAttributeMaxDynamicSharedMemorySize, ATT_SMEM);

    lam_kernel<<<1, 32>>>(lq1, lk1, lq2, lk2);

    qkv_kernel<<<dim3(64, 8, 3), 128>>>(x_q, x_kv, Wq, bq, Wk, bk, Wv, bv);

    attn_kernel<<<dim3(32, 4, 4), 128, ATT_SMEM>>>(coords_q, coords_k, alpha, rpe);

    proj_kernel<<<dim3(64, 8), 128>>>(Wp, bp, out);
}

// round 9
// speedup vs baseline: 1.0216x; 1.0216x over previous
#include <cuda_runtime.h>

#define DIMC 512
#define NH   8
#define HD   64
#define BATCH 4
#define NQ   1024
#define NKV  1024

// ---------------- scratch (device globals: no allocation allowed) ----------
__device__ float g_q [BATCH*NH*NQ *HD];   // pre-rounded to tf32 bit pattern
__device__ float g_k [BATCH*NH*NKV*HD];   // "
__device__ float g_v [BATCH*NH*NKV*HD];   // "
__device__ float g_xo[BATCH*NQ*DIMC];
__device__ float g_lam[NH/2];

// ---------------- lambda ---------------------------------------------------
__global__ void lam_kernel(const float* __restrict__ lq1, const float* __restrict__ lk1,
                           const float* __restrict__ lq2, const float* __restrict__ lk2)
{
    int p = threadIdx.x;
    if (p < NH/2) {
        float a = 0.f, c = 0.f;
        for (int d = 0; d < HD; d++) {
            a += lq1[p*HD+d] * lk1[p*HD+d];
            c += lq2[p*HD+d] * lk2[p*HD+d];
        }
        g_lam[p] = __expf(a) - __expf(c) + 0.8f;
    }
}

// ---------------- tf32 / async helpers -------------------------------------
__device__ __forceinline__ unsigned f2tf32(float x) {
    unsigned r;
    asm("cvt.rna.tf32.f32 %0, %1;" : "=r"(r) : "f"(x));
    return r;
}

__device__ __forceinline__ void mma_tf32(float c[4],
    unsigned a0, unsigned a1, unsigned a2, unsigned a3,
    unsigned b0, unsigned b1)
{
    asm volatile(
        "mma.sync.aligned.m16n8k8.row.col.f32.tf32.tf32.f32 "
        "{%0,%1,%2,%3},{%4,%5,%6,%7},{%8,%9},{%0,%1,%2,%3};\n"
        : "+f"(c[0]), "+f"(c[1]), "+f"(c[2]), "+f"(c[3])
        : "r"(a0), "r"(a1), "r"(a2), "r"(a3), "r"(b0), "r"(b1));
}

__device__ __forceinline__ void cpasync16(const void* smem_dst, const void* gmem_src) {
    unsigned s = (unsigned)__cvta_generic_to_shared(smem_dst);
    asm volatile("cp.async.cg.shared.global [%0], [%1], 16;\n" :: "r"(s), "l"(gmem_src));
}
__device__ __forceinline__ void cpasync_commit() {
    asm volatile("cp.async.commit_group;\n");
}
__device__ __forceinline__ void cpasync_wait0() {
    asm volatile("cp.async.wait_group 0;\n");
}

// ---------------- tf32 GEMM: C = A[M,K] @ W[N,K]^T + bias ------------------
// CTA tile 128x64, 4 warps (2x2), warp tile 64x32, K-step 16 (2 x k8). (R5 shape)
// mode 0: C row-major [M,512] fp32 ; mode 1: C into [B,H,N,HD], tf32-pre-rounded
__device__ __forceinline__ void gemm_body(
    const float* __restrict__ A, const float* __restrict__ W,
    const float* __restrict__ bias, float* __restrict__ C,
    int mode, int bm, int bn)
{
    __shared__ unsigned As[16][136];   // [k][m], m<128
    __shared__ unsigned Ws[16][72];    // [k][n], n<64

    int tid  = threadIdx.x;
    int wid  = tid >> 5;
    int lane = tid & 31;
    int g    = lane >> 2;
    int tg   = lane & 3;
    int wm   = (wid >> 1) * 64;
    int wn   = (wid & 1) * 32;

    float acc[4][4][4];
#pragma unroll
    for (int mf = 0; mf < 4; mf++)
#pragma unroll
        for (int nf = 0; nf < 4; nf++)
#pragma unroll
            for (int e = 0; e < 4; e++) acc[mf][nf][e] = 0.f;

    const float* Arow = A + (size_t)(bm + tid) * DIMC;
    int nW = tid & 63, khW = tid >> 6;
    const float* Wrow = W + (size_t)(bn + nW) * DIMC + khW * 8;

    float4 av[4], wv[2];
#pragma unroll
    for (int i = 0; i < 4; i++) av[i] = *(const float4*)(Arow + i*4);
    wv[0] = *(const float4*)(Wrow);
    wv[1] = *(const float4*)(Wrow + 4);

    for (int k0 = 0; k0 < DIMC; k0 += 16) {
#pragma unroll
        for (int i = 0; i < 4; i++) {
            As[i*4+0][tid] = f2tf32(av[i].x);
            As[i*4+1][tid] = f2tf32(av[i].y);
            As[i*4+2][tid] = f2tf32(av[i].z);
            As[i*4+3][tid] = f2tf32(av[i].w);
        }
        Ws[khW*8+0][nW] = f2tf32(wv[0].x);
        Ws[khW*8+1][nW] = f2tf32(wv[0].y);
        Ws[khW*8+2][nW] = f2tf32(wv[0].z);
        Ws[khW*8+3][nW] = f2tf32(wv[0].w);
        Ws[khW*8+4][nW] = f2tf32(wv[1].x);
        Ws[khW*8+5][nW] = f2tf32(wv[1].y);
        Ws[khW*8+6][nW] = f2tf32(wv[1].z);
        Ws[khW*8+7][nW] = f2tf32(wv[1].w);
        __syncthreads();

        if (k0 + 16 < DIMC) {
#pragma unroll
            for (int i = 0; i < 4; i++)
                av[i] = *(const float4*)(Arow + k0 + 16 + i*4);
            wv[0] = *(const float4*)(Wrow + k0 + 16);
            wv[1] = *(const float4*)(Wrow + k0 + 20);
        }

#pragma unroll
        for (int ko = 0; ko < 16; ko += 8) {
            unsigned af[4][4], bf[4][2];
#pragma unroll
            for (int mf = 0; mf < 4; mf++) {
                int m0 = wm + mf*16 + g;
                af[mf][0] = As[ko+tg  ][m0];
                af[mf][1] = As[ko+tg  ][m0+8];
                af[mf][2] = As[ko+tg+4][m0];
                af[mf][3] = As[ko+tg+4][m0+8];
            }
#pragma unroll
            for (int nf = 0; nf < 4; nf++) {
                int n0 = wn + nf*8 + g;
                bf[nf][0] = Ws[ko+tg  ][n0];
                bf[nf][1] = Ws[ko+tg+4][n0];
            }
#pragma unroll
            for (int mf = 0; mf < 4; mf++)
#pragma unroll
                for (int nf = 0; nf < 4; nf++)
                    mma_tf32(acc[mf][nf], af[mf][0], af[mf][1], af[mf][2], af[mf][3],
                             bf[nf][0], bf[nf][1]);
        }
        __syncthreads();
    }

#pragma unroll
    for (int nf = 0; nf < 4; nf++) {
        int c0 = bn + wn + nf*8 + 2*tg;
        float b0 = bias[c0], b1 = bias[c0+1];
#pragma unroll
        for (int mf = 0; mf < 4; mf++) {
            int r0 = bm + wm + mf*16 + g;
            float2 o0 = {acc[mf][nf][0] + b0, acc[mf][nf][1] + b1};
            float2 o1 = {acc[mf][nf][2] + b0, acc[mf][nf][3] + b1};
            if (mode == 0) {
                *(float2*)(C + (size_t)r0*DIMC + c0)     = o0;
                *(float2*)(C + (size_t)(r0+8)*DIMC + c0) = o1;
            } else {
                o0.x = __uint_as_float(f2tf32(o0.x));
                o0.y = __uint_as_float(f2tf32(o0.y));
                o1.x = __uint_as_float(f2tf32(o1.x));
                o1.y = __uint_as_float(f2tf32(o1.y));
                int h = c0 >> 6, hd = c0 & 63;
                int b_  = r0 >> 10, nq = r0 & 1023;
                *(float2*)(C + (((size_t)(b_*NH + h)*NQ + nq)*HD + hd)) = o0;
                b_ = (r0+8) >> 10; nq = (r0+8) & 1023;
                *(float2*)(C + (((size_t)(b_*NH + h)*NQ + nq)*HD + hd)) = o1;
            }
        }
    }
}

__global__ __launch_bounds__(128) void qkv_kernel(
    const float* __restrict__ x_q, const float* __restrict__ x_kv,
    const float* __restrict__ Wq, const float* __restrict__ bq,
    const float* __restrict__ Wk, const float* __restrict__ bk,
    const float* __restrict__ Wv, const float* __restrict__ bv)
{
    int z = blockIdx.z;
    const float* A    = (z == 0) ? x_q : x_kv;
    const float* W    = (z == 0) ? Wq : (z == 1) ? Wk : Wv;
    const float* bias = (z == 0) ? bq : (z == 1) ? bk : bv;
    float* C          = (z == 0) ? g_q : (z == 1) ? g_k : g_v;
    gemm_body(A, W, bias, C, 1, blockIdx.x*128, blockIdx.y*64);
}

__global__ __launch_bounds__(128) void proj_kernel(
    const float* __restrict__ Wp, const float* __restrict__ bp, float* __restrict__ out)
{
    gemm_body(g_xo, Wp, bp, out, 0, blockIdx.x*128, blockIdx.y*64);
}

// ---------------- tensor-core differential flash attention -----------------
// R5 structure: grid (NQ/64, NH/2, B), 256 threads (8 warps), BQ=64.
// K/V tiles double-buffered + cp.async prefetch of tile i+1 issued before
// tile i's compute. Q/K/V pre-rounded tf32: staging is bit copy.
// Score duty : warp w -> head (w>>2), m-strip (w&3)*16
// PV duty    : warp w -> m-strip (w>>1)*16, n-half (w&1)*32
#define ASTRIDE 68
#define TILEW (64*ASTRIDE)

__global__ __launch_bounds__(256, 1) void attn_kernel(
    const int* __restrict__ coords_q, const int* __restrict__ coords_k,
    const float* __restrict__ alpha_map, const float* __restrict__ rpe)
{
    extern __shared__ __align__(16) unsigned su[];
    unsigned* sQ1 = su;                   // [64][68]
    unsigned* sQ2 = sQ1 + TILEW;
    unsigned* sK1 = sQ2 + TILEW;          // [2][64][68]
    unsigned* sK2 = sK1 + 2*TILEW;
    unsigned* sV1 = sK2 + 2*TILEW;
    unsigned* sV2 = sV1 + 2*TILEW;
    unsigned* sS1 = sV2 + 2*TILEW;        // P tiles
    unsigned* sS2 = sS1 + TILEW;
    float* sC1 = (float*)(sS2 + TILEW);   // [64] corrections
    float* sC2 = sC1 + 64;
    float* sL1 = sC2 + 64;                // [64] final l
    float* sL2 = sL1 + 64;
    int*   sCk = (int*)(sL2 + 64);        // [2][128]

    int tid  = threadIdx.x;
    int w    = tid >> 5;
    int lane = tid & 31;
    int g    = lane >> 2;
    int tg   = lane & 3;

    int qb = blockIdx.x * 64;
    int p  = blockIdx.y;
    int b  = blockIdx.z;
    int h1 = p, h2 = p + 4;

    int sh  = w >> 2;
    int sm0 = (w & 3) * 16;
    int pm0 = (w >> 1) * 16;
    int pn0 = (w & 1) * 32;

    const unsigned* q1g = (const unsigned*)(g_q + ((size_t)(b*NH+h1)*NQ + qb)*HD);
    const unsigned* q2g = (const unsigned*)(g_q + ((size_t)(b*NH+h2)*NQ + qb)*HD);
    const unsigned* k1base = (const unsigned*)(g_k + ((size_t)(b*NH+h1)*NKV)*HD);
    const unsigned* k2base = (const unsigned*)(g_k + ((size_t)(b*NH+h2)*NKV)*HD);
    const unsigned* v1base = (const unsigned*)(g_v + ((size_t)(b*NH+h1)*NKV)*HD);
    const unsigned* v2base = (const unsigned*)(g_v + ((size_t)(b*NH+h2)*NKV)*HD);

    // ---- prologue: async-stage Q and K/V tile 0 (buffer 0) ----
    for (int c = tid; c < 1024; c += 256) {
        int row = c >> 4, seg = (c & 15) * 4;
        int po = row*ASTRIDE + seg;
        int go = row*HD + seg;
        cpasync16(&sQ1[po], q1g + go);
        cpasync16(&sQ2[po], q2g + go);
        cpasync16(&sK1[po], k1base + go);
        cpasync16(&sK2[po], k2base + go);
        cpasync16(&sV1[po], v1base + go);
        cpasync16(&sV2[po], v2base + go);
    }
    if (tid < 128) sCk[tid] = coords_k[(size_t)b*NKV*2 + tid];
    cpasync_commit();

    // score-duty coords (rows sm0+g, sm0+g+8)
    int sr0 = sm0 + g, sr1 = sm0 + g + 8;
    int cqx0 = coords_q[((size_t)b*NQ + qb + sr0)*2];
    int cqy0 = coords_q[((size_t)b*NQ + qb + sr0)*2 + 1];
    int cqx1 = coords_q[((size_t)b*NQ + qb + sr1)*2];
    int cqy1 = coords_q[((size_t)b*NQ + qb + sr1)*2 + 1];
    int hh = sh ? h2 : h1;

    float mOld0 = -1e30f, mOld1 = -1e30f, lRun0 = 0.f, lRun1 = 0.f;

    float pacc[3][4][4];
#pragma unroll
    for (int pr = 0; pr < 3; pr++)
#pragma unroll
        for (int nt = 0; nt < 4; nt++)
#pragma unroll
            for (int e = 0; e < 4; e++) pacc[pr][nt][e] = 0.f;

    const unsigned* Qs = sh ? sQ2 : sQ1;
    unsigned* Ss       = sh ? sS2 : sS1;
    float* sCa         = sh ? sC2 : sC1;

    cpasync_wait0();
    __syncthreads();

    for (int t = 0; t < NKV/64; t++) {
        int cur = t & 1, nxt = cur ^ 1;

        // ---- issue prefetch of tile t+1 into the other buffer ----
        if (t + 1 < NKV/64) {
            int kb1 = (t + 1) * 64;
            for (int c = tid; c < 1024; c += 256) {
                int row = c >> 4, seg = (c & 15) * 4;
                int po = nxt*TILEW + row*ASTRIDE + seg;
                int go = (kb1 + row)*HD + seg;
                cpasync16(&sK1[po], k1base + go);
                cpasync16(&sK2[po], k2base + go);
                cpasync16(&sV1[po], v1base + go);
                cpasync16(&sV2[po], v2base + go);
            }
            if (tid < 128) sCk[nxt*128 + tid] = coords_k[((size_t)b*NKV + kb1)*2 + tid];
            cpasync_commit();
        }

        const unsigned* Ks = (sh ? sK2 : sK1) + cur*TILEW;
        const int* ck = sCk + cur*128;

        // ---- scores: m16 strip x 64 kv via mma ----
        float sc[8][4];
#pragma unroll
        for (int nt = 0; nt < 8; nt++)
#pragma unroll
            for (int e = 0; e < 4; e++) sc[nt][e] = 0.f;

#pragma unroll
        for (int ko = 0; ko < 64; ko += 8) {
            unsigned a0 = Qs[(sm0+g  )*ASTRIDE + ko+tg];
            unsigned a1 = Qs[(sm0+g+8)*ASTRIDE + ko+tg];
            unsigned a2 = Qs[(sm0+g  )*ASTRIDE + ko+tg+4];
            unsigned a3 = Qs[(sm0+g+8)*ASTRIDE + ko+tg+4];
#pragma unroll
            for (int nt = 0; nt < 8; nt++) {
                unsigned b0 = Ks[(8*nt+g)*ASTRIDE + ko+tg];
                unsigned b1 = Ks[(8*nt+g)*ASTRIDE + ko+tg+4];
                mma_tf32(sc[nt], a0, a1, a2, a3, b0, b1);
            }
        }

        // ---- scale + RPE bias ----
#pragma unroll
        for (int nt = 0; nt < 8; nt++) {
#pragma unroll
            for (int u = 0; u < 2; u++) {
                int col = 8*nt + 2*tg + u;
                int ckx = ck[col*2], cky = ck[col*2+1];
                int r0 = min(max(cqx0 - ckx + 128, 0), 256);
                int r1 = min(max(cqy0 - cky + 128, 0), 256);
                sc[nt][u] = sc[nt][u]*0.125f + __ldg(&rpe[(r0*257 + r1)*NH + hh]);
                r0 = min(max(cqx1 - ckx + 128, 0), 256);
                r1 = min(max(cqy1 - cky + 128, 0), 256);
                sc[nt][2+u] = sc[nt][2+u]*0.125f + __ldg(&rpe[(r0*257 + r1)*NH + hh]);
            }
        }

        // ---- online softmax (rows sr0, sr1; quad reduction) ----
        float rm0 = sc[0][0], rm1 = sc[0][2];
#pragma unroll
        for (int nt = 0; nt < 8; nt++) {
            rm0 = fmaxf(rm0, fmaxf(sc[nt][0], sc[nt][1]));
            rm1 = fmaxf(rm1, fmaxf(sc[nt][2], sc[nt][3]));
        }
#pragma unroll
        for (int o = 1; o < 4; o <<= 1) {
            rm0 = fmaxf(rm0, __shfl_xor_sync(0xffffffffu, rm0, o));
            rm1 = fmaxf(rm1, __shfl_xor_sync(0xffffffffu, rm1, o));
        }
        float nm0 = fmaxf(mOld0, rm0), nm1 = fmaxf(mOld1, rm1);
        float corr0 = __expf(mOld0 - nm0), corr1 = __expf(mOld1 - nm1);

        float sum0 = 0.f, sum1 = 0.f;
#pragma unroll
        for (int nt = 0; nt < 8; nt++) {
#pragma unroll
            for (int u = 0; u < 2; u++) {
                int col = 8*nt + 2*tg + u;
                float e0 = __expf(sc[nt][u]   - nm0); sum0 += e0;
                float e1 = __expf(sc[nt][2+u] - nm1); sum1 += e1;
                Ss[sr0*ASTRIDE + col] = f2tf32(e0);
                Ss[sr1*ASTRIDE + col] = f2tf32(e1);
            }
        }
#pragma unroll
        for (int o = 1; o < 4; o <<= 1) {
            sum0 += __shfl_xor_sync(0xffffffffu, sum0, o);
            sum1 += __shfl_xor_sync(0xffffffffu, sum1, o);
        }
        lRun0 = lRun0*corr0 + sum0;
        lRun1 = lRun1*corr1 + sum1;
        mOld0 = nm0; mOld1 = nm1;
        if (tg == 0) { sCa[sr0] = corr0; sCa[sr1] = corr1; }
        __syncthreads();

        // ---- PV: rescale accumulators, then mma-accumulate this tile ----
        const unsigned* V1 = sV1 + cur*TILEW;
        const unsigned* V2 = sV2 + cur*TILEW;
        float c1r0 = sC1[pm0+g], c1r1 = sC1[pm0+g+8];
        float c2r0 = sC2[pm0+g], c2r1 = sC2[pm0+g+8];
#pragma unroll
        for (int nt = 0; nt < 4; nt++) {
            pacc[0][nt][0] *= c1r0; pacc[0][nt][1] *= c1r0;
            pacc[0][nt][2] *= c1r1; pacc[0][nt][3] *= c1r1;
            pacc[1][nt][0] *= c2r0; pacc[1][nt][1] *= c2r0;
            pacc[1][nt][2] *= c2r1; pacc[1][nt][3] *= c2r1;
            pacc[2][nt][0] *= c2r0; pacc[2][nt][1] *= c2r0;
            pacc[2][nt][2] *= c2r1; pacc[2][nt][3] *= c2r1;
        }

#pragma unroll
        for (int ko = 0; ko < 64; ko += 8) {
            unsigned p1a0 = sS1[(pm0+g  )*ASTRIDE + ko+tg];
            unsigned p1a1 = sS1[(pm0+g+8)*ASTRIDE + ko+tg];
            unsigned p1a2 = sS1[(pm0+g  )*ASTRIDE + ko+tg+4];
            unsigned p1a3 = sS1[(pm0+g+8)*ASTRIDE + ko+tg+4];
            unsigned p2a0 = sS2[(pm0+g  )*ASTRIDE + ko+tg];
            unsigned p2a1 = sS2[(pm0+g+8)*ASTRIDE + ko+tg];
            unsigned p2a2 = sS2[(pm0+g  )*ASTRIDE + ko+tg+4];
            unsigned p2a3 = sS2[(pm0+g+8)*ASTRIDE + ko+tg+4];
#pragma unroll
            for (int nt = 0; nt < 4; nt++) {
                int n0 = pn0 + 8*nt;
                unsigned bv10 = V1[(ko+tg  )*ASTRIDE + n0+g];
                unsigned bv11 = V1[(ko+tg+4)*ASTRIDE + n0+g];
                unsigned bv20 = V2[(ko+tg  )*ASTRIDE + n0+g];
                unsigned bv21 = V2[(ko+tg+4)*ASTRIDE + n0+g];
                mma_tf32(pacc[0][nt], p1a0, p1a1, p1a2, p1a3, bv10, bv11);
                mma_tf32(pacc[1][nt], p2a0, p2a1, p2a2, p2a3, bv10, bv11);
                mma_tf32(pacc[2][nt], p2a0, p2a1, p2a2, p2a3, bv20, bv21);
            }
        }
        cpasync_wait0();
        __syncthreads();
    }

    // publish final l
    if (tg == 0) {
        if (sh == 0) { sL1[sr0] = lRun0; sL1[sr1] = lRun1; }
        else         { sL2[sr0] = lRun0; sL2[sr1] = lRun1; }
    }
    __syncthreads();

    // ---- epilogue (PV layout) ----
    float lam = g_lam[p];
    int r_0 = pm0 + g, r_1 = pm0 + g + 8;
    float l1_0 = sL1[r_0], l1_1 = sL1[r_1];
    float l2_0 = sL2[r_0], l2_1 = sL2[r_1];
    float al0 = alpha_map[(size_t)b*NQ + qb + r_0];
    float al1 = alpha_map[(size_t)b*NQ + qb + r_1];
    float w1_0 = (1.f + al0) / l1_0, w2_0 = -al0 * lam / l2_0, i2_0 = 1.f / l2_0;
    float w1_1 = (1.f + al1) / l1_1, w2_1 = -al1 * lam / l2_1, i2_1 = 1.f / l2_1;

    float* o0 = g_xo + ((size_t)(b*NQ + qb + r_0))*DIMC;
    float* o1 = g_xo + ((size_t)(b*NQ + qb + r_1))*DIMC;
#pragma unroll
    for (int nt = 0; nt < 4; nt++) {
        int col = pn0 + 8*nt + 2*tg;
        float2 t;
        t.x = w1_0*pacc[0][nt][0] + w2_0*pacc[1][nt][0];
        t.y = w1_0*pacc[0][nt][1] + w2_0*pacc[1][nt][1];
        *(float2*)(o0 + h1*HD + col) = t;
        t.x = w1_1*pacc[0][nt][2] + w2_1*pacc[1][nt][2];
        t.y = w1_1*pacc[0][nt][3] + w2_1*pacc[1][nt][3];
        *(float2*)(o1 + h1*HD + col) = t;
        t.x = i2_0*pacc[2][nt][0];
        t.y = i2_0*pacc[2][nt][1];
        *(float2*)(o0 + h2*HD + col) = t;
        t.x = i2_1*pacc[2][nt][2];
        t.y = i2_1*pacc[2][nt][3];
        *(float2*)(o1 + h2*HD + col) = t;
    }
}

// ---------------- launch ---------------------------------------------------
#define ATT_SMEM (12*TILEW*4 + 4*64*4 + 2*128*4)

extern "C" void kernel_launch(void* const* d_in, const int* in_sizes, int n_in,
                              void* d_out, int out_size)
{
    const float* x_q      = (const float*)d_in[0];
    const float* x_kv     = (const float*)d_in[1];
    const int*   coords_q = (const int*)  d_in[2];
    const int*   coords_k = (const int*)  d_in[3];
    const float* alpha    = (const float*)d_in[4];
    const float* Wq       = (const float*)d_in[5];
    const float* bq       = (const float*)d_in[6];
    const float* Wk       = (const float*)d_in[7];
    const float* bk       = (const float*)d_in[8];
    const float* Wv       = (const float*)d_in[9];
    const float* bv       = (const float*)d_in[10];
    const float* lq1      = (const float*)d_in[11];
    const float* lk1      = (const float*)d_in[12];
    const float* lq2      = (const float*)d_in[13];
    const float* lk2      = (const float*)d_in[14];
    const float* rpe      = (const float*)d_in[15];
    const float* Wp       = (const float*)d_in[16];
    const float* bp       = (const float*)d_in[17];
    float* out = (float*)d_out;

    cudaFuncSetAttribute(attn_kernel,
                         cudaFuncAttributeMaxDynamicSharedMemorySize, ATT_SMEM);

    lam_kernel<<<1, 32>>>(lq1, lk1, lq2, lk2);

    qkv_kernel<<<dim3(32, 8, 3), 128>>>(x_q, x_kv, Wq, bq, Wk, bk, Wv, bv);

    attn_kernel<<<dim3(16, 4, 4), 256, ATT_SMEM>>>(coords_q, coords_k, alpha, rpe);

    proj_kernel<<<dim3(32, 8), 128>>>(Wp, bp, out);
}

// round 10
// speedup vs baseline: 1.2709x; 1.2440x over previous
#include <cuda_runtime.h>

#define DIMC 512
#define NH   8
#define HD   64
#define BATCH 4
#define NQ   1024
#define NKV  1024

// ---------------- scratch (device globals: no allocation allowed) ----------
__device__ float g_q [BATCH*NH*NQ *HD];   // pre-rounded to tf32 bit pattern
__device__ float g_k [BATCH*NH*NKV*HD];   // "
__device__ float g_v [BATCH*NH*NKV*HD];   // "
__device__ float g_xo[BATCH*NQ*DIMC];
__device__ float g_lam[NH/2];

// ---------------- lambda ---------------------------------------------------
__global__ void lam_kernel(const float* __restrict__ lq1, const float* __restrict__ lk1,
                           const float* __restrict__ lq2, const float* __restrict__ lk2)
{
    int p = threadIdx.x;
    if (p < NH/2) {
        float a = 0.f, c = 0.f;
        for (int d = 0; d < HD; d++) {
            a += lq1[p*HD+d] * lk1[p*HD+d];
            c += lq2[p*HD+d] * lk2[p*HD+d];
        }
        g_lam[p] = __expf(a) - __expf(c) + 0.8f;
    }
}

// ---------------- tf32 helpers ---------------------------------------------
__device__ __forceinline__ unsigned f2tf32(float x) {
    unsigned r;
    asm("cvt.rna.tf32.f32 %0, %1;" : "=r"(r) : "f"(x));
    return r;
}

__device__ __forceinline__ void mma_tf32(float c[4],
    unsigned a0, unsigned a1, unsigned a2, unsigned a3,
    unsigned b0, unsigned b1)
{
    asm volatile(
        "mma.sync.aligned.m16n8k8.row.col.f32.tf32.tf32.f32 "
        "{%0,%1,%2,%3},{%4,%5,%6,%7},{%8,%9},{%0,%1,%2,%3};\n"
        : "+f"(c[0]), "+f"(c[1]), "+f"(c[2]), "+f"(c[3])
        : "r"(a0), "r"(a1), "r"(a2), "r"(a3), "r"(b0), "r"(b1));
}

// ---------------- tf32 GEMM: C = A[M,K] @ W[N,K]^T + bias ------------------
// CTA tile 128x64 (R5 shape), 4 warps (2x2), warp tile 64x32, K-step 16.
// NEW vs R5: double-buffered smem -> ONE barrier per k-step instead of two.
// mode 0: C row-major [M,512] fp32 ; mode 1: C into [B,H,N,HD], tf32-pre-rounded
__device__ __forceinline__ void gemm_body(
    const float* __restrict__ A, const float* __restrict__ W,
    const float* __restrict__ bias, float* __restrict__ C,
    int mode, int bm, int bn)
{
    __shared__ unsigned As[2][16][136];   // [buf][k][m]
    __shared__ unsigned Ws[2][16][72];    // [buf][k][n]

    int tid  = threadIdx.x;
    int wid  = tid >> 5;
    int lane = tid & 31;
    int g    = lane >> 2;
    int tg   = lane & 3;
    int wm   = (wid >> 1) * 64;
    int wn   = (wid & 1) * 32;

    float acc[4][4][4];
#pragma unroll
    for (int mf = 0; mf < 4; mf++)
#pragma unroll
        for (int nf = 0; nf < 4; nf++)
#pragma unroll
            for (int e = 0; e < 4; e++) acc[mf][nf][e] = 0.f;

    const float* Arow = A + (size_t)(bm + tid) * DIMC;
    int nW = tid & 63, khW = tid >> 6;
    const float* Wrow = W + (size_t)(bn + nW) * DIMC + khW * 8;

    float4 av[4], wv[2];
#pragma unroll
    for (int i = 0; i < 4; i++) av[i] = *(const float4*)(Arow + i*4);
    wv[0] = *(const float4*)(Wrow);
    wv[1] = *(const float4*)(Wrow + 4);

    // stage buffer 0
#pragma unroll
    for (int i = 0; i < 4; i++) {
        As[0][i*4+0][tid] = f2tf32(av[i].x);
        As[0][i*4+1][tid] = f2tf32(av[i].y);
        As[0][i*4+2][tid] = f2tf32(av[i].z);
        As[0][i*4+3][tid] = f2tf32(av[i].w);
    }
    Ws[0][khW*8+0][nW] = f2tf32(wv[0].x);
    Ws[0][khW*8+1][nW] = f2tf32(wv[0].y);
    Ws[0][khW*8+2][nW] = f2tf32(wv[0].z);
    Ws[0][khW*8+3][nW] = f2tf32(wv[0].w);
    Ws[0][khW*8+4][nW] = f2tf32(wv[1].x);
    Ws[0][khW*8+5][nW] = f2tf32(wv[1].y);
    Ws[0][khW*8+6][nW] = f2tf32(wv[1].z);
    Ws[0][khW*8+7][nW] = f2tf32(wv[1].w);
    __syncthreads();

    for (int k0 = 0; k0 < DIMC; k0 += 16) {
        int  buf  = (k0 >> 4) & 1;
        bool more = (k0 + 16 < DIMC);
        if (more) {
#pragma unroll
            for (int i = 0; i < 4; i++)
                av[i] = *(const float4*)(Arow + k0 + 16 + i*4);
            wv[0] = *(const float4*)(Wrow + k0 + 16);
            wv[1] = *(const float4*)(Wrow + k0 + 20);
        }

        // compute on current buffer
#pragma unroll
        for (int ko = 0; ko < 16; ko += 8) {
            unsigned af[4][4], bf[4][2];
#pragma unroll
            for (int mf = 0; mf < 4; mf++) {
                int m0 = wm + mf*16 + g;
                af[mf][0] = As[buf][ko+tg  ][m0];
                af[mf][1] = As[buf][ko+tg  ][m0+8];
                af[mf][2] = As[buf][ko+tg+4][m0];
                af[mf][3] = As[buf][ko+tg+4][m0+8];
            }
#pragma unroll
            for (int nf = 0; nf < 4; nf++) {
                int n0 = wn + nf*8 + g;
                bf[nf][0] = Ws[buf][ko+tg  ][n0];
                bf[nf][1] = Ws[buf][ko+tg+4][n0];
            }
#pragma unroll
            for (int mf = 0; mf < 4; mf++)
#pragma unroll
                for (int nf = 0; nf < 4; nf++)
                    mma_tf32(acc[mf][nf], af[mf][0], af[mf][1], af[mf][2], af[mf][3],
                             bf[nf][0], bf[nf][1]);
        }

        if (more) {
            int nb = buf ^ 1;   // safe: all warps done with nb since last barrier
#pragma unroll
            for (int i = 0; i < 4; i++) {
                As[nb][i*4+0][tid] = f2tf32(av[i].x);
                As[nb][i*4+1][tid] = f2tf32(av[i].y);
                As[nb][i*4+2][tid] = f2tf32(av[i].z);
                As[nb][i*4+3][tid] = f2tf32(av[i].w);
            }
            Ws[nb][khW*8+0][nW] = f2tf32(wv[0].x);
            Ws[nb][khW*8+1][nW] = f2tf32(wv[0].y);
            Ws[nb][khW*8+2][nW] = f2tf32(wv[0].z);
            Ws[nb][khW*8+3][nW] = f2tf32(wv[0].w);
            Ws[nb][khW*8+4][nW] = f2tf32(wv[1].x);
            Ws[nb][khW*8+5][nW] = f2tf32(wv[1].y);
            Ws[nb][khW*8+6][nW] = f2tf32(wv[1].z);
            Ws[nb][khW*8+7][nW] = f2tf32(wv[1].w);
            __syncthreads();
        }
    }

#pragma unroll
    for (int nf = 0; nf < 4; nf++) {
        int c0 = bn + wn + nf*8 + 2*tg;
        float b0 = bias[c0], b1 = bias[c0+1];
#pragma unroll
        for (int mf = 0; mf < 4; mf++) {
            int r0 = bm + wm + mf*16 + g;
            float2 o0 = {acc[mf][nf][0] + b0, acc[mf][nf][1] + b1};
            float2 o1 = {acc[mf][nf][2] + b0, acc[mf][nf][3] + b1};
            if (mode == 0) {
                *(float2*)(C + (size_t)r0*DIMC + c0)     = o0;
                *(float2*)(C + (size_t)(r0+8)*DIMC + c0) = o1;
            } else {
                o0.x = __uint_as_float(f2tf32(o0.x));
                o0.y = __uint_as_float(f2tf32(o0.y));
                o1.x = __uint_as_float(f2tf32(o1.x));
                o1.y = __uint_as_float(f2tf32(o1.y));
                int h = c0 >> 6, hd = c0 & 63;
                int b_  = r0 >> 10, nq = r0 & 1023;
                *(float2*)(C + (((size_t)(b_*NH + h)*NQ + nq)*HD + hd)) = o0;
                b_ = (r0+8) >> 10; nq = (r0+8) & 1023;
                *(float2*)(C + (((size_t)(b_*NH + h)*NQ + nq)*HD + hd)) = o1;
            }
        }
    }
}

__global__ __launch_bounds__(128) void qkv_kernel(
    const float* __restrict__ x_q, const float* __restrict__ x_kv,
    const float* __restrict__ Wq, const float* __restrict__ bq,
    const float* __restrict__ Wk, const float* __restrict__ bk,
    const float* __restrict__ Wv, const float* __restrict__ bv)
{
    int z = blockIdx.z;
    const float* A    = (z == 0) ? x_q : x_kv;
    const float* W    = (z == 0) ? Wq : (z == 1) ? Wk : Wv;
    const float* bias = (z == 0) ? bq : (z == 1) ? bk : bv;
    float* C          = (z == 0) ? g_q : (z == 1) ? g_k : g_v;
    gemm_body(A, W, bias, C, 1, blockIdx.x*128, blockIdx.y*64);
}

__global__ __launch_bounds__(128) void proj_kernel(
    const float* __restrict__ Wp, const float* __restrict__ bp, float* __restrict__ out)
{
    gemm_body(g_xo, Wp, bp, out, 0, blockIdx.x*128, blockIdx.y*64);
}

// ---------------- tensor-core differential flash attention -----------------
// R5-exact structure: grid (NQ/64, NH/2, B), 256 threads, single-buffered
// LDG+STS staging (cp.async regressed in R9; reverted).
// NEW: (a) staging is pure uint4 bit-copy (Q/K/V pre-rounded tf32);
//      (b) RPE gathers issued BEFORE the score mma loop (addresses depend
//          only on coords) so L2 latency hides under 64 MMAs + LDS.
#define ASTRIDE 68
#define TILEW (64*ASTRIDE)

__global__ __launch_bounds__(256, 1) void attn_kernel(
    const int* __restrict__ coords_q, const int* __restrict__ coords_k,
    const float* __restrict__ alpha_map, const float* __restrict__ rpe)
{
    extern __shared__ __align__(16) unsigned su[];
    unsigned* sQ1 = su;                   // [64][68]
    unsigned* sQ2 = sQ1 + TILEW;
    unsigned* sK1 = sQ2 + TILEW;
    unsigned* sK2 = sK1 + TILEW;
    unsigned* sV1 = sK2 + TILEW;
    unsigned* sV2 = sV1 + TILEW;
    unsigned* sS1 = sV2 + TILEW;          // P tiles (tf32)
    unsigned* sS2 = sS1 + TILEW;
    float* sC1 = (float*)(sS2 + TILEW);   // [64] corrections
    float* sC2 = sC1 + 64;
    float* sL1 = sC2 + 64;                // [64] final l
    float* sL2 = sL1 + 64;
    int*   sCk = (int*)(sL2 + 64);        // [128]

    int tid  = threadIdx.x;
    int w    = tid >> 5;
    int lane = tid & 31;
    int g    = lane >> 2;
    int tg   = lane & 3;

    int qb = blockIdx.x * 64;
    int p  = blockIdx.y;
    int b  = blockIdx.z;
    int h1 = p, h2 = p + 4;

    int sh  = w >> 2;          // score head
    int sm0 = (w & 3) * 16;    // score m-strip
    int pm0 = (w >> 1) * 16;   // PV m-strip
    int pn0 = (w & 1) * 32;    // PV n-half

    const unsigned* q1g = (const unsigned*)(g_q + ((size_t)(b*NH+h1)*NQ + qb)*HD);
    const unsigned* q2g = (const unsigned*)(g_q + ((size_t)(b*NH+h2)*NQ + qb)*HD);
    const unsigned* k1base = (const unsigned*)(g_k + ((size_t)(b*NH+h1)*NKV)*HD);
    const unsigned* k2base = (const unsigned*)(g_k + ((size_t)(b*NH+h2)*NKV)*HD);
    const unsigned* v1base = (const unsigned*)(g_v + ((size_t)(b*NH+h1)*NKV)*HD);
    const unsigned* v2base = (const unsigned*)(g_v + ((size_t)(b*NH+h2)*NKV)*HD);

    // ---- stage Q (bit copy) ----
    for (int c = tid; c < 1024; c += 256) {
        int row = c >> 4, seg = (c & 15) * 4;
        *(uint4*)&sQ1[row*ASTRIDE+seg] = *(const uint4*)(q1g + row*HD + seg);
        *(uint4*)&sQ2[row*ASTRIDE+seg] = *(const uint4*)(q2g + row*HD + seg);
    }

    int sr0 = sm0 + g, sr1 = sm0 + g + 8;
    int cqx0 = coords_q[((size_t)b*NQ + qb + sr0)*2];
    int cqy0 = coords_q[((size_t)b*NQ + qb + sr0)*2 + 1];
    int cqx1 = coords_q[((size_t)b*NQ + qb + sr1)*2];
    int cqy1 = coords_q[((size_t)b*NQ + qb + sr1)*2 + 1];
    int hh = sh ? h2 : h1;

    float mOld0 = -1e30f, mOld1 = -1e30f, lRun0 = 0.f, lRun1 = 0.f;

    float pacc[3][4][4];
#pragma unroll
    for (int pr = 0; pr < 3; pr++)
#pragma unroll
        for (int nt = 0; nt < 4; nt++)
#pragma unroll
            for (int e = 0; e < 4; e++) pacc[pr][nt][e] = 0.f;

    const unsigned* Qs = sh ? sQ2 : sQ1;
    const unsigned* Ks = sh ? sK2 : sK1;
    unsigned* Ss       = sh ? sS2 : sS1;
    float* sCa         = sh ? sC2 : sC1;

    for (int kb = 0; kb < NKV; kb += 64) {
        // ---- stage K/V (bit copy) + coords ----
        for (int c = tid; c < 1024; c += 256) {
            int row = c >> 4, seg = (c & 15) * 4;
            int go = (kb + row)*HD + seg;
            *(uint4*)&sK1[row*ASTRIDE+seg] = *(const uint4*)(k1base + go);
            *(uint4*)&sK2[row*ASTRIDE+seg] = *(const uint4*)(k2base + go);
            *(uint4*)&sV1[row*ASTRIDE+seg] = *(const uint4*)(v1base + go);
            *(uint4*)&sV2[row*ASTRIDE+seg] = *(const uint4*)(v2base + go);
        }
        if (tid < 128) sCk[tid] = coords_k[((size_t)b*NKV + kb)*2 + tid];
        __syncthreads();

        // ---- issue RPE gathers EARLY (independent of mma results) ----
        float bias[8][4];
#pragma unroll
        for (int nt = 0; nt < 8; nt++) {
#pragma unroll
            for (int u = 0; u < 2; u++) {
                int col = 8*nt + 2*tg + u;
                int ckx = sCk[col*2], cky = sCk[col*2+1];
                int r0 = min(max(cqx0 - ckx + 128, 0), 256);
                int r1 = min(max(cqy0 - cky + 128, 0), 256);
                bias[nt][u] = __ldg(&rpe[(r0*257 + r1)*NH + hh]);
                r0 = min(max(cqx1 - ckx + 128, 0), 256);
                r1 = min(max(cqy1 - cky + 128, 0), 256);
                bias[nt][2+u] = __ldg(&rpe[(r0*257 + r1)*NH + hh]);
            }
        }

        // ---- scores: m16 strip x 64 kv via mma (overlaps RPE L2 latency) ----
        float sc[8][4];
#pragma unroll
        for (int nt = 0; nt < 8; nt++)
#pragma unroll
            for (int e = 0; e < 4; e++) sc[nt][e] = 0.f;

#pragma unroll
        for (int ko = 0; ko < 64; ko += 8) {
            unsigned a0 = Qs[(sm0+g  )*ASTRIDE + ko+tg];
            unsigned a1 = Qs[(sm0+g+8)*ASTRIDE + ko+tg];
            unsigned a2 = Qs[(sm0+g  )*ASTRIDE + ko+tg+4];
            unsigned a3 = Qs[(sm0+g+8)*ASTRIDE + ko+tg+4];
#pragma unroll
            for (int nt = 0; nt < 8; nt++) {
                unsigned b0 = Ks[(8*nt+g)*ASTRIDE + ko+tg];
                unsigned b1 = Ks[(8*nt+g)*ASTRIDE + ko+tg+4];
                mma_tf32(sc[nt], a0, a1, a2, a3, b0, b1);
            }
        }

        // ---- scale + bias ----
#pragma unroll
        for (int nt = 0; nt < 8; nt++)
#pragma unroll
            for (int e = 0; e < 4; e++)
                sc[nt][e] = sc[nt][e]*0.125f + bias[nt][e];

        // ---- online softmax (rows sr0, sr1; quad reduction) ----
        float rm0 = sc[0][0], rm1 = sc[0][2];
#pragma unroll
        for (int nt = 0; nt < 8; nt++) {
            rm0 = fmaxf(rm0, fmaxf(sc[nt][0], sc[nt][1]));
            rm1 = fmaxf(rm1, fmaxf(sc[nt][2], sc[nt][3]));
        }
#pragma unroll
        for (int o = 1; o < 4; o <<= 1) {
            rm0 = fmaxf(rm0, __shfl_xor_sync(0xffffffffu, rm0, o));
            rm1 = fmaxf(rm1, __shfl_xor_sync(0xffffffffu, rm1, o));
        }
        float nm0 = fmaxf(mOld0, rm0), nm1 = fmaxf(mOld1, rm1);
        float corr0 = __expf(mOld0 - nm0), corr1 = __expf(mOld1 - nm1);

        float sum0 = 0.f, sum1 = 0.f;
#pragma unroll
        for (int nt = 0; nt < 8; nt++) {
#pragma unroll
            for (int u = 0; u < 2; u++) {
                int col = 8*nt + 2*tg + u;
                float e0 = __expf(sc[nt][u]   - nm0); sum0 += e0;
                float e1 = __expf(sc[nt][2+u] - nm1); sum1 += e1;
                Ss[sr0*ASTRIDE + col] = f2tf32(e0);
                Ss[sr1*ASTRIDE + col] = f2tf32(e1);
            }
        }
#pragma unroll
        for (int o = 1; o < 4; o <<= 1) {
            sum0 += __shfl_xor_sync(0xffffffffu, sum0, o);
            sum1 += __shfl_xor_sync(0xffffffffu, sum1, o);
        }
        lRun0 = lRun0*corr0 + sum0;
        lRun1 = lRun1*corr1 + sum1;
        mOld0 = nm0; mOld1 = nm1;
        if (tg == 0) { sCa[sr0] = corr0; sCa[sr1] = corr1; }
        __syncthreads();

        // ---- PV: rescale accumulators, then mma-accumulate this tile ----
        float c1r0 = sC1[pm0+g], c1r1 = sC1[pm0+g+8];
        float c2r0 = sC2[pm0+g], c2r1 = sC2[pm0+g+8];
#pragma unroll
        for (int nt = 0; nt < 4; nt++) {
            pacc[0][nt][0] *= c1r0; pacc[0][nt][1] *= c1r0;
            pacc[0][nt][2] *= c1r1; pacc[0][nt][3] *= c1r1;
            pacc[1][nt][0] *= c2r0; pacc[1][nt][1] *= c2r0;
            pacc[1][nt][2] *= c2r1; pacc[1][nt][3] *= c2r1;
            pacc[2][nt][0] *= c2r0; pacc[2][nt][1] *= c2r0;
            pacc[2][nt][2] *= c2r1; pacc[2][nt][3] *= c2r1;
        }

#pragma unroll
        for (int ko = 0; ko < 64; ko += 8) {
            unsigned p1a0 = sS1[(pm0+g  )*ASTRIDE + ko+tg];
            unsigned p1a1 = sS1[(pm0+g+8)*ASTRIDE + ko+tg];
            unsigned p1a2 = sS1[(pm0+g  )*ASTRIDE + ko+tg+4];
            unsigned p1a3 = sS1[(pm0+g+8)*ASTRIDE + ko+tg+4];
            unsigned p2a0 = sS2[(pm0+g  )*ASTRIDE + ko+tg];
            unsigned p2a1 = sS2[(pm0+g+8)*ASTRIDE + ko+tg];
            unsigned p2a2 = sS2[(pm0+g  )*ASTRIDE + ko+tg+4];
            unsigned p2a3 = sS2[(pm0+g+8)*ASTRIDE + ko+tg+4];
#pragma unroll
            for (int nt = 0; nt < 4; nt++) {
                int n0 = pn0 + 8*nt;
                unsigned bv10 = sV1[(ko+tg  )*ASTRIDE + n0+g];
                unsigned bv11 = sV1[(ko+tg+4)*ASTRIDE + n0+g];
                unsigned bv20 = sV2[(ko+tg  )*ASTRIDE + n0+g];
                unsigned bv21 = sV2[(ko+tg+4)*ASTRIDE + n0+g];
                mma_tf32(pacc[0][nt], p1a0, p1a1, p1a2, p1a3, bv10, bv11);
                mma_tf32(pacc[1][nt], p2a0, p2a1, p2a2, p2a3, bv10, bv11);
                mma_tf32(pacc[2][nt], p2a0, p2a1, p2a2, p2a3, bv20, bv21);
            }
        }
        __syncthreads();
    }

    // publish final l
    if (tg == 0) {
        if (sh == 0) { sL1[sr0] = lRun0; sL1[sr1] = lRun1; }
        else         { sL2[sr0] = lRun0; sL2[sr1] = lRun1; }
    }
    __syncthreads();

    // ---- epilogue (PV layout) ----
    float lam = g_lam[p];
    int r_0 = pm0 + g, r_1 = pm0 + g + 8;
    float l1_0 = sL1[r_0], l1_1 = sL1[r_1];
    float l2_0 = sL2[r_0], l2_1 = sL2[r_1];
    float al0 = alpha_map[(size_t)b*NQ + qb + r_0];
    float al1 = alpha_map[(size_t)b*NQ + qb + r_1];
    float w1_0 = (1.f + al0) / l1_0, w2_0 = -al0 * lam / l2_0, i2_0 = 1.f / l2_0;
    float w1_1 = (1.f + al1) / l1_1, w2_1 = -al1 * lam / l2_1, i2_1 = 1.f / l2_1;

    float* o0 = g_xo + ((size_t)(b*NQ + qb + r_0))*DIMC;
    float* o1 = g_xo + ((size_t)(b*NQ + qb + r_1))*DIMC;
#pragma unroll
    for (int nt = 0; nt < 4; nt++) {
        int col = pn0 + 8*nt + 2*tg;
        float2 t;
        t.x = w1_0*pacc[0][nt][0] + w2_0*pacc[1][nt][0];
        t.y = w1_0*pacc[0][nt][1] + w2_0*pacc[1][nt][1];
        *(float2*)(o0 + h1*HD + col) = t;
        t.x = w1_1*pacc[0][nt][2] + w2_1*pacc[1][nt][2];
        t.y = w1_1*pacc[0][nt][3] + w2_1*pacc[1][nt][3];
        *(float2*)(o1 + h1*HD + col) = t;
        t.x = i2_0*pacc[2][nt][0];
        t.y = i2_0*pacc[2][nt][1];
        *(float2*)(o0 + h2*HD + col) = t;
        t.x = i2_1*pacc[2][nt][2];
        t.y = i2_1*pacc[2][nt][3];
        *(float2*)(o1 + h2*HD + col) = t;
    }
}

// ---------------- launch ---------------------------------------------------
#define ATT_SMEM (8*TILEW*4 + 4*64*4 + 128*4)

extern "C" void kernel_launch(void* const* d_in, const int* in_sizes, int n_in,
                              void* d_out, int out_size)
{
    const float* x_q      = (const float*)d_in[0];
    const float* x_kv     = (const float*)d_in[1];
    const int*   coords_q = (const int*)  d_in[2];
    const int*   coords_k = (const int*)  d_in[3];
    const float* alpha    = (const float*)d_in[4];
    const float* Wq       = (const float*)d_in[5];
    const float* bq       = (const float*)d_in[6];
    const float* Wk       = (const float*)d_in[7];
    const float* bk       = (const float*)d_in[8];
    const float* Wv       = (const float*)d_in[9];
    const float* bv       = (const float*)d_in[10];
    const float* lq1      = (const float*)d_in[11];
    const float* lk1      = (const float*)d_in[12];
    const float* lq2      = (const float*)d_in[13];
    const float* lk2      = (const float*)d_in[14];
    const float* rpe      = (const float*)d_in[15];
    const float* Wp       = (const float*)d_in[16];
    const float* bp       = (const float*)d_in[17];
    float* out = (float*)d_out;

    cudaFuncSetAttribute(attn_kernel,
                         cudaFuncAttributeMaxDynamicSharedMemorySize, ATT_SMEM);

    lam_kernel<<<1, 32>>>(lq1, lk1, lq2, lk2);

    qkv_kernel<<<dim3(32, 8, 3), 128>>>(x_q, x_kv, Wq, bq, Wk, bk, Wv, bv);

    attn_kernel<<<dim3(16, 4, 4), 256, ATT_SMEM>>>(coords_q, coords_k, alpha, rpe);

    proj_kernel<<<dim3(32, 8), 128>>>(Wp, bp, out);
}